// round 6
// baseline (speedup 1.0000x reference)
#include <cuda_runtime.h>
#include <cstdint>

#define NTS   2048
#define KXV   256
#define NYV   8192
#define NTH   1024
#define CSZ   8
#define CHUNK (NYV/CSZ)   /* 1024 Y vars per CTA, 1 per thread */

__device__ __forceinline__ uint32_t s2u(const void* p){
    return (uint32_t)__cvta_generic_to_shared(p);
}
__device__ __forceinline__ uint32_t mapa_u32(uint32_t la, uint32_t rank){
    uint32_t ra;
    asm("mapa.shared::cluster.u32 %0, %1, %2;" : "=r"(ra) : "r"(la), "r"(rank));
    return ra;
}
__device__ __forceinline__ void mbar_init(uint32_t a, uint32_t cnt){
    asm volatile("mbarrier.init.shared.b64 [%0], %1;" :: "r"(a), "r"(cnt) : "memory");
}
__device__ __forceinline__ void remote_st(uint32_t ra, float v){
    asm volatile("st.shared::cluster.f32 [%0], %1;" :: "r"(ra), "f"(v) : "memory");
}
__device__ __forceinline__ void remote_arrive(uint32_t ra){
    asm volatile("mbarrier.arrive.release.cluster.shared::cluster.b64 _, [%0];"
                 :: "r"(ra) : "memory");
}
__device__ __forceinline__ void mbar_wait(uint32_t a, uint32_t parity){
    asm volatile(
        "{\n\t"
        ".reg .pred P;\n"
        "WL_%=:\n\t"
        "mbarrier.try_wait.parity.acquire.cluster.shared::cta.b64 P, [%0], %1;\n\t"
        "@!P bra WL_%=;\n\t"
        "}"
        :: "r"(a), "r"(parity) : "memory");
}

__global__ __launch_bounds__(NTH, 1) __cluster_dims__(CSZ, 1, 1)
void lorenz96_kernel(const float* __restrict__ X0,
                     const float* __restrict__ Y0,
                     const float* __restrict__ coupling,
                     const float* __restrict__ pF,
                     const float* __restrict__ ph,
                     const float* __restrict__ pc,
                     const float* __restrict__ pdt,
                     float* __restrict__ xhist,
                     float* __restrict__ yhist)
{
    __shared__ float sY[2][CHUNK];
    __shared__ float sX[2][KXV];
    __shared__ float mboxL[4];       // slot s: left neighbor's chunk-last value (y[j0-1])
    __shared__ float mboxR[4][2];    // slot s: right neighbor's first two values
    __shared__ __align__(8) unsigned long long mbarL[4];
    __shared__ __align__(8) unsigned long long mbarR[4];

    const int t = threadIdx.x;
    const bool isX = (t < KXV);

    uint32_t rank;
    asm("mov.u32 %0, %%cluster_ctarank;" : "=r"(rank));
    const uint32_t lrank = (rank + CSZ - 1) % CSZ;
    const uint32_t rrank = (rank + 1) % CSZ;

    const float F  = *pF;
    const float h  = *ph;
    const float c  = *pc;
    const float dt = *pdt;

    // frozen bit-exact constant recipe (matches the XLA lowering)
    const float a      = __fmul_rn(__fmul_rn(-1.0f, c), 32.0f);   // (-c)*J
    const float hcJ    = __fdiv_rn(__fmul_rn(h, c), 32.0f);       // (h*c)/J
    const float halfdt = __fmul_rn(0.5f, dt);
    const float dt6    = __fdiv_rn(dt, 6.0f);

    const int jg = rank * CHUNK + t;   // global Y index of this thread's var
    const int xi = jg >> 5;            // X index feeding this Y var (0..255)

    // mbarrier init: mbarR gets 2 arrivals/phase (right neighbor threads 0 & 1),
    // mbarL gets 1 (left neighbor thread NTH-1).
    if (t == 0) {
        #pragma unroll
        for (int s = 0; s < 4; s++) {
            mbar_init(s2u(&mbarL[s]), 1);
            mbar_init(s2u(&mbarR[s]), 2);
        }
    }
    __syncthreads();
    // all CTAs' mbarriers must exist before any remote arrive
    asm volatile("barrier.cluster.arrive.aligned;" ::: "memory");
    asm volatile("barrier.cluster.wait.aligned;"   ::: "memory");

    // precomputed remote addresses (producer side)
    uint32_t ra_dR = 0, ra_bR = 0, ra_dL = 0, ra_bL = 0;
    if (t < 2) {                       // this CTA's vars 0,1 feed LEFT neighbor's right mailbox
        ra_dR = mapa_u32(s2u(&mboxR[0][t]), lrank);
        ra_bR = mapa_u32(s2u(&mbarR[0]),    lrank);
    }
    if (t == NTH - 1) {                // this CTA's last var feeds RIGHT neighbor's left mailbox
        ra_dL = mapa_u32(s2u(&mboxL[0]), rrank);
        ra_bL = mapa_u32(s2u(&mbarL[0]), rrank);
    }

    // ---- init state from row 0 ----
    float yb = Y0[jg];
    float yc = yb;
    float d1 = 0.f, d2 = 0.f;
    yhist[jg] = yb;                    // row 0 output
    sY[0][t] = yb;

    float xb = 0.f, xc = 0.f, xd1 = 0.f, xd2 = 0.f, coup_next = 0.f;
    if (isX) {
        xb = X0[t];
        xc = xb;
        sX[0][t] = xb;
        coup_next = coupling[t];       // coupling row 0 drives step 1
        if (rank == 0) xhist[t] = xb;
    }

    // initial slot-3 delivery: base-state edges (consumed at step 1, substep 0, parity 0)
    if (t < 2)       { remote_st(ra_dR + 3 * 8, yc); remote_arrive(ra_bR + 3 * 8); }
    if (t == NTH-1)  { remote_st(ra_dL + 3 * 4, yc); remote_arrive(ra_bL + 3 * 8); }
    __syncthreads();

    for (int n = 1; n < NTS; n++) {
        const float coup = coup_next;
        if (isX && n < NTS - 1) coup_next = coupling[n * KXV + t];
        const uint32_t par = (uint32_t)((n - 1) & 1);

        #pragma unroll
        for (int s = 0; s < 4; s++) {
            const int rb = s & 1;
            const int wb = rb ^ 1;
            const int ps = (s + 3) & 3;          // slot carrying the stage we consume

            // halo reads (edge threads synchronize with neighbors first)
            float ym1, yp1, yp2;
            if (t == 0) {
                mbar_wait(s2u(&mbarL[ps]), par);
                ym1 = mboxL[ps];
            } else {
                ym1 = sY[rb][t - 1];
            }
            if (t >= NTH - 2) {
                mbar_wait(s2u(&mbarR[ps]), par);
            }
            yp1 = (t == NTH - 1) ? mboxR[ps][0] : sY[rb][t + 1];
            yp2 = (t == NTH - 1) ? mboxR[ps][1]
                : ((t == NTH - 2) ? mboxR[ps][0] : sY[rb][t + 2]);
            const float xs = sX[rb][xi];

            // Ydot — frozen op order:
            //   t5 = fma(a*y+1, (y+2 - y-1), -(c*y)); dn = fma(hcJ, x, t5)
            const float t1 = __fsub_rn(yp2, ym1);
            const float t2 = __fmul_rn(a, yp1);
            const float t4 = __fmul_rn(c, yc);
            const float t5 = __fmaf_rn(t2, t1, -t4);
            const float dn = __fmaf_rn(hcJ, xs, t5);

            float xdn = 0.f;
            if (isX) {
                const float xm2 = sX[rb][(t + KXV - 2) & (KXV - 1)];
                const float xm1 = sX[rb][(t + KXV - 1) & (KXV - 1)];
                const float xp1 = sX[rb][(t + 1) & (KXV - 1)];
                const float u1 = __fsub_rn(xp1, xm2);
                const float u3 = __fmaf_rn(xm1, u1, -xc);
                const float u4 = __fadd_rn(u3, F);
                xdn = __fadd_rn(u4, coup);
            }

            // stage updates — frozen recipe
            if (s == 0) {
                d1 = dn;
                yc = __fmaf_rn(halfdt, dn, yb);
                if (isX) { xd1 = xdn; xc = __fmaf_rn(halfdt, xdn, xb); }
            } else if (s == 1) {
                d2 = dn;
                yc = __fmaf_rn(halfdt, dn, yb);
                if (isX) { xd2 = xdn; xc = __fmaf_rn(halfdt, xdn, xb); }
            } else if (s == 2) {
                d2 = __fadd_rn(d2, dn);
                yc = __fmaf_rn(dt, dn, yb);
                if (isX) { xd2 = __fadd_rn(xd2, xdn); xc = __fmaf_rn(dt, xdn, xb); }
            } else {
                const float sA  = __fadd_rn(d1, dn);
                const float sum = __fmaf_rn(2.0f, d2, sA);
                yc = __fmaf_rn(dt6, sum, yb);
                yb = yc;
                if (isX) {
                    const float xA  = __fadd_rn(xd1, xdn);
                    const float xsm = __fmaf_rn(2.0f, xd2, xA);
                    xc = __fmaf_rn(dt6, xsm, xb);
                    xb = xc;
                }
            }

            // publish stage locally + edge deliveries to neighbors
            sY[wb][t] = yc;
            if (isX) sX[wb][t] = xc;
            if (t < 2)      { remote_st(ra_dR + s * 8, yc); remote_arrive(ra_bR + s * 8); }
            if (t == NTH-1) { remote_st(ra_dL + s * 4, yc); remote_arrive(ra_bL + s * 8); }
            __syncthreads();
        }

        // history row n
        yhist[(size_t)n * NYV + jg] = yc;
        if (isX && rank == 0) xhist[(size_t)n * KXV + t] = xc;
    }

    // keep smem alive until all in-flight remote deliveries have landed
    asm volatile("barrier.cluster.arrive.aligned;" ::: "memory");
    asm volatile("barrier.cluster.wait.aligned;"   ::: "memory");
}

extern "C" void kernel_launch(void* const* d_in, const int* in_sizes, int n_in,
                              void* d_out, int out_size)
{
    const float* X0  = (const float*)d_in[0];
    const float* Y0  = (const float*)d_in[1];
    const float* cp  = (const float*)d_in[2];
    const float* pF  = (const float*)d_in[3];
    const float* ph  = (const float*)d_in[4];
    // d_in[5] = b (unused by the math)
    const float* pc  = (const float*)d_in[6];
    const float* pdt = (const float*)d_in[7];

    float* out   = (float*)d_out;
    float* xhist = out;                       // [2048, 256]
    float* yhist = out + (size_t)NTS * KXV;   // [2048, 8192]

    lorenz96_kernel<<<CSZ, NTH>>>(X0, Y0, cp, pF, ph, pc, pdt, xhist, yhist);
}

// round 9
// speedup vs baseline: 2.3334x; 2.3334x over previous
#include <cuda_runtime.h>
#include <cstdint>

#define NTS    2048
#define KXV    256
#define NYV    8192
#define NTH    1024
#define CSZ    8
#define CHUNK  1024
#define GSTEP  4            /* steps between cross-CTA exchanges */
#define GL     (4*GSTEP)    /* 16 left ghosts  */
#define GR     (8*GSTEP)    /* 32 right ghosts */
#define NG     (GL+GR)      /* 48 */
#define EXT    (GL+CHUNK+GR)/* 1072 extended cells */
#define GBASE  256          /* ghost duty on threads [GBASE, GBASE+NG) */

__device__ __forceinline__ uint32_t s2u(const void* p){
    return (uint32_t)__cvta_generic_to_shared(p);
}
__device__ __forceinline__ uint32_t mapa_u32(uint32_t la, uint32_t rank){
    uint32_t ra;
    asm("mapa.shared::cluster.u32 %0, %1, %2;" : "=r"(ra) : "r"(la), "r"(rank));
    return ra;
}
__device__ __forceinline__ void mbar_init(uint32_t a, uint32_t cnt){
    asm volatile("mbarrier.init.shared.b64 [%0], %1;" :: "r"(a), "r"(cnt) : "memory");
}
__device__ __forceinline__ void remote_st(uint32_t ra, float v){
    asm volatile("st.shared::cluster.f32 [%0], %1;" :: "r"(ra), "f"(v) : "memory");
}
__device__ __forceinline__ void remote_arrive(uint32_t ra){
    asm volatile("mbarrier.arrive.release.cluster.shared::cluster.b64 _, [%0];"
                 :: "r"(ra) : "memory");
}
__device__ __forceinline__ void mbar_wait(uint32_t a, uint32_t parity){
    asm volatile(
        "{\n\t"
        ".reg .pred P;\n"
        "WL_%=:\n\t"
        "mbarrier.try_wait.parity.acquire.cluster.shared::cta.b64 P, [%0], %1;\n\t"
        "@!P bra WL_%=;\n\t"
        "}"
        :: "r"(a), "r"(parity) : "memory");
}

__global__ __launch_bounds__(NTH, 1) __cluster_dims__(CSZ, 1, 1)
void lorenz96_kernel(const float* __restrict__ X0,
                     const float* __restrict__ Y0,
                     const float* __restrict__ coupling,
                     const float* __restrict__ pF,
                     const float* __restrict__ ph,
                     const float* __restrict__ pc,
                     const float* __restrict__ pdt,
                     float* __restrict__ xhist,
                     float* __restrict__ yhist)
{
    // extended Y stage arrays: 1 pad left + EXT cells + 2 pads right, double buffered
    __shared__ float sYe[2][EXT + 3];
    __shared__ float sX [2][KXV];
    __shared__ float mbxL[2][GL];    // from LEFT neighbor: its last GL owned
    __shared__ float mbxR[2][GR];    // from RIGHT neighbor: its first GR owned
    __shared__ __align__(8) unsigned long long mbarL[2];
    __shared__ __align__(8) unsigned long long mbarR[2];

    const int t = threadIdx.x;
    const bool isX = (t < KXV);

    uint32_t rank;
    asm("mov.u32 %0, %%cluster_ctarank;" : "=r"(rank));
    const uint32_t lrank = (rank + CSZ - 1) % CSZ;
    const uint32_t rrank = (rank + 1) % CSZ;

    const float F  = *pF;
    const float h  = *ph;
    const float c  = *pc;
    const float dt = *pdt;

    // frozen bit-exact constant recipe
    const float a      = __fmul_rn(__fmul_rn(-1.0f, c), 32.0f);
    const float hcJ    = __fdiv_rn(__fmul_rn(h, c), 32.0f);
    const float halfdt = __fmul_rn(0.5f, dt);
    const float dt6    = __fdiv_rn(dt, 6.0f);

    const int jg  = (int)rank * CHUNK + t;   // global index of owned Y var
    const int xiO = jg >> 5;
    const int xo  = GL + t;                  // extended index of owned cell

    // ghost duty: threads [256, 304)
    const bool hasG = (t >= GBASE) && (t < GBASE + NG);
    const int  gi   = t - GBASE;                                   // 0..47
    const int  gx   = hasG ? ((gi < GL) ? gi : (GL + CHUNK + (gi - GL))) : 0;
    const int  gg   = ((int)rank * CHUNK + gx - GL + NYV) & (NYV - 1);
    const int  xiG  = gg >> 5;

    // ---- mbarrier + pad init ----
    if (t == 0) {
        #pragma unroll
        for (int b = 0; b < 2; b++) {
            mbar_init(s2u(&mbarL[b]), GL);
            mbar_init(s2u(&mbarR[b]), GR);
        }
        sYe[0][0] = 0.f;        sYe[1][0] = 0.f;
        sYe[0][EXT+1] = 0.f;    sYe[1][EXT+1] = 0.f;
        sYe[0][EXT+2] = 0.f;    sYe[1][EXT+2] = 0.f;
    }
    __syncthreads();
    asm volatile("barrier.cluster.arrive.aligned;" ::: "memory");
    asm volatile("barrier.cluster.wait.aligned;"   ::: "memory");

    // remote mailbox addresses (producer side)
    uint32_t raR_d = 0, raR_b = 0, raL_d = 0, raL_b = 0;
    if (t < GR) {                       // my first GR owned -> LEFT neighbor's right ghosts
        raR_d = mapa_u32(s2u(&mbxR[0][t]), lrank);
        raR_b = mapa_u32(s2u(&mbarR[0]),   lrank);
    }
    if (t >= CHUNK - GL) {              // my last GL owned -> RIGHT neighbor's left ghosts
        raL_d = mapa_u32(s2u(&mbxL[0][t - (CHUNK - GL)]), rrank);
        raL_b = mapa_u32(s2u(&mbarL[0]),                  rrank);
    }

    // ---- state init (row 0) ----
    float yb = Y0[jg];
    float yc = yb, d1 = 0.f, d2 = 0.f;
    yhist[jg] = yb;
    sYe[0][xo + 1] = yb;

    float gyb = 0.f, gyc = 0.f, gd1 = 0.f, gd2 = 0.f;
    if (hasG) {
        gyb = Y0[gg];
        gyc = gyb;
        sYe[0][gx + 1] = gyb;
    }

    float xb = 0.f, xc = 0.f, xd1 = 0.f, xd2 = 0.f, coup_next = 0.f;
    if (isX) {
        xb = X0[t]; xc = xb;
        sX[0][t] = xb;
        coup_next = coupling[t];
        if (rank == 0) xhist[t] = xb;
    }
    __syncthreads();

    int xrnd = 0;   // exchange round counter

    for (int n = 1; n < NTS; n++) {
        const float coup = coup_next;
        if (isX && n < NTS - 1) coup_next = coupling[n * KXV + t];

        #pragma unroll
        for (int s = 0; s < 4; s++) {
            const int rb = s & 1;
            const int wb = rb ^ 1;

            // ---- owned cell derivative ----
            const float ym1 = sYe[rb][xo];       // x-1  (+1 pad offset)
            const float yp1 = sYe[rb][xo + 2];   // x+1
            const float yp2 = sYe[rb][xo + 3];   // x+2
            const float xs  = sX[rb][xiO];
            const float t1 = __fsub_rn(yp2, ym1);
            const float t2 = __fmul_rn(a, yp1);
            const float t4 = __fmul_rn(c, yc);
            const float t5 = __fmaf_rn(t2, t1, -t4);
            const float dn = __fmaf_rn(hcJ, xs, t5);

            // ---- ghost cell derivative (predicated) ----
            float gdn = 0.f;
            if (hasG) {
                const float gm1 = sYe[rb][gx];
                const float gp1 = sYe[rb][gx + 2];
                const float gp2 = sYe[rb][gx + 3];
                const float gxs = sX[rb][xiG];
                const float g1 = __fsub_rn(gp2, gm1);
                const float g2 = __fmul_rn(a, gp1);
                const float g4 = __fmul_rn(c, gyc);
                const float g5 = __fmaf_rn(g2, g1, -g4);
                gdn = __fmaf_rn(hcJ, gxs, g5);
            }

            // ---- X derivative (predicated) ----
            float xdn = 0.f;
            if (isX) {
                const float xm2 = sX[rb][(t + KXV - 2) & (KXV - 1)];
                const float xm1 = sX[rb][(t + KXV - 1) & (KXV - 1)];
                const float xp1 = sX[rb][(t + 1) & (KXV - 1)];
                const float u1 = __fsub_rn(xp1, xm2);
                const float u3 = __fmaf_rn(xm1, u1, -xc);
                const float u4 = __fadd_rn(u3, F);
                xdn = __fadd_rn(u4, coup);
            }

            // ---- stage updates (frozen recipe) ----
            if (s == 0) {
                d1 = dn;                        yc  = __fmaf_rn(halfdt, dn,  yb);
                if (hasG) { gd1 = gdn;          gyc = __fmaf_rn(halfdt, gdn, gyb); }
                if (isX)  { xd1 = xdn;          xc  = __fmaf_rn(halfdt, xdn, xb); }
            } else if (s == 1) {
                d2 = dn;                        yc  = __fmaf_rn(halfdt, dn,  yb);
                if (hasG) { gd2 = gdn;          gyc = __fmaf_rn(halfdt, gdn, gyb); }
                if (isX)  { xd2 = xdn;          xc  = __fmaf_rn(halfdt, xdn, xb); }
            } else if (s == 2) {
                d2 = __fadd_rn(d2, dn);         yc  = __fmaf_rn(dt, dn,  yb);
                if (hasG) { gd2 = __fadd_rn(gd2, gdn); gyc = __fmaf_rn(dt, gdn, gyb); }
                if (isX)  { xd2 = __fadd_rn(xd2, xdn); xc  = __fmaf_rn(dt, xdn, xb); }
            } else {
                const float sA  = __fadd_rn(d1, dn);
                const float sum = __fmaf_rn(2.0f, d2, sA);
                yc = __fmaf_rn(dt6, sum, yb);  yb = yc;
                if (hasG) {
                    const float gA  = __fadd_rn(gd1, gdn);
                    const float gsm = __fmaf_rn(2.0f, gd2, gA);
                    gyc = __fmaf_rn(dt6, gsm, gyb);  gyb = gyc;
                }
                if (isX) {
                    const float xA  = __fadd_rn(xd1, xdn);
                    const float xsm = __fmaf_rn(2.0f, xd2, xA);
                    xc = __fmaf_rn(dt6, xsm, xb);  xb = xc;
                }
            }

            // publish stage
            sYe[wb][xo + 1] = yc;
            if (hasG) sYe[wb][gx + 1] = gyc;
            if (isX)  sX[wb][t] = xc;
            __syncthreads();
        }

        // ---- history row n ----
        yhist[(size_t)n * NYV + jg] = yc;
        if (isX && rank == 0) xhist[(size_t)n * KXV + t] = xc;

        // ---- cross-CTA ghost exchange every GSTEP steps ----
        if ((n & (GSTEP - 1)) == 0 && n < NTS - 1) {
            const int      buf = xrnd & 1;
            const uint32_t par = (uint32_t)((xrnd >> 1) & 1);

            // send new base edges (yc == post-step base)
            if (t < GR) {
                remote_st(raR_d + (uint32_t)buf * (GR * 4), yc);
                remote_arrive(raR_b + (uint32_t)buf * 8);
            }
            if (t >= CHUNK - GL) {
                remote_st(raL_d + (uint32_t)buf * (GL * 4), yc);
                remote_arrive(raL_b + (uint32_t)buf * 8);
            }

            // receive: ghost threads refresh ghost base
            if (hasG) {
                if (gi < GL) {
                    mbar_wait(s2u(&mbarL[buf]), par);
                    gyb = mbxL[buf][gi];
                } else {
                    mbar_wait(s2u(&mbarR[buf]), par);
                    gyb = mbxR[buf][gi - GL];
                }
                gyc = gyb;
                sYe[0][gx + 1] = gyb;     // base buffer is buf0 at step start
            }
            xrnd++;
            __syncthreads();
        }
    }

    // keep smem alive until all in-flight remote traffic has landed
    asm volatile("barrier.cluster.arrive.aligned;" ::: "memory");
    asm volatile("barrier.cluster.wait.aligned;"   ::: "memory");
}

extern "C" void kernel_launch(void* const* d_in, const int* in_sizes, int n_in,
                              void* d_out, int out_size)
{
    const float* X0  = (const float*)d_in[0];
    const float* Y0  = (const float*)d_in[1];
    const float* cp  = (const float*)d_in[2];
    const float* pF  = (const float*)d_in[3];
    const float* ph  = (const float*)d_in[4];
    // d_in[5] = b (unused by the math)
    const float* pc  = (const float*)d_in[6];
    const float* pdt = (const float*)d_in[7];

    float* out   = (float*)d_out;
    float* xhist = out;                       // [2048, 256]
    float* yhist = out + (size_t)NTS * KXV;   // [2048, 8192]

    lorenz96_kernel<<<CSZ, NTH>>>(X0, Y0, cp, pF, ph, pc, pdt, xhist, yhist);
}